// round 15
// baseline (speedup 1.0000x reference)
#include <cuda_runtime.h>
#include <math.h>
#include <stdint.h>

// Problem constants
#define PD   768        // model dim
#define NB   8          // batch
#define NP   1024       // seq len
#define NH   12         // heads
#define NKV  6          // kv heads
#define HD   64         // head dim
#define BPROWS (NB*NP)          // 8192
#define KVDIM  (NKV*HD)         // 384
#define YLEN   (NP*HD)          // 65536
#define MTOT   (NH*YLEN)        // 786432
#define LOG2E  1.44269504088896340736f

// ---------------- scratch (static device memory; no allocations) -------------
__device__ float pgqa_Q[BPROWS*PD];      // q*(log2e/8), tf32-rounded, d-permuted
__device__ float pgqa_K[BPROWS*KVDIM];   // tf32-rounded, d-permuted
__device__ float pgqa_V[BPROWS*KVDIM];   // tf32-rounded, natural order
__device__ float pgqa_Att[BPROWS*PD];    // attention out, [B*P, 768]
__device__ float pgqa_M[MTOT];           // regenerated uniform matrix [12, 65536]
__device__ float pgqa_rmean[NB*NH];
__device__ float pgqa_rstd[NB*NH];
__device__ float pgqa_mmean[NH];
__device__ float pgqa_mistd[NH];
__device__ double pgqa_msum[96];
__device__ double pgqa_msum2[96];
__device__ double pgqa_rsum[NB*NH*16];   // [bh][qtile] deterministic slots
__device__ double pgqa_rsum2[NB*NH*16];

// ---------------- JAX threefry2x32, key = (0, 42) ----------------------------
__device__ __forceinline__ void pgqa_threefry(unsigned x0, unsigned x1,
                                              unsigned& o0, unsigned& o1) {
    const unsigned ks0 = 0u, ks1 = 42u, ks2 = 0x1BD11BDAu ^ 42u;
    x0 += ks0; x1 += ks1;
#define PGQA_R(r) { x0 += x1; x1 = (x1 << (r)) | (x1 >> (32 - (r))); x1 ^= x0; }
    PGQA_R(13) PGQA_R(15) PGQA_R(26) PGQA_R(6)
    x0 += ks1; x1 += ks2 + 1u;
    PGQA_R(17) PGQA_R(29) PGQA_R(16) PGQA_R(24)
    x0 += ks2; x1 += ks0 + 2u;
    PGQA_R(13) PGQA_R(15) PGQA_R(26) PGQA_R(6)
    x0 += ks0; x1 += ks1 + 3u;
    PGQA_R(17) PGQA_R(29) PGQA_R(16) PGQA_R(24)
    x0 += ks1; x1 += ks2 + 4u;
    PGQA_R(13) PGQA_R(15) PGQA_R(26) PGQA_R(6)
    x0 += ks2; x1 += ks0 + 5u;
#undef PGQA_R
    o0 = x0; o1 = x1;
}
__device__ __forceinline__ float pgqa_uniform(unsigned bits) {
    return __uint_as_float((bits >> 9) | 0x3f800000u) - 1.0f;
}
__device__ __forceinline__ float pgqa_m_at(unsigned i) {
    unsigned o0, o1;
    pgqa_threefry(0u, i, o0, o1);
    return pgqa_uniform(o0 ^ o1);
}

__device__ __forceinline__ unsigned pgqa_tf32r(float f) {
    unsigned u; asm("cvt.rna.tf32.f32 %0, %1;" : "=r"(u) : "f"(f)); return u;
}
__device__ __forceinline__ void pgqa_mma_tf32(float& c0, float& c1, float& c2, float& c3,
                                              unsigned a0, unsigned a1, unsigned a2, unsigned a3,
                                              unsigned b0, unsigned b1) {
    asm volatile(
        "mma.sync.aligned.m16n8k8.row.col.f32.tf32.tf32.f32 "
        "{%0,%1,%2,%3}, {%4,%5,%6,%7}, {%8,%9}, {%0,%1,%2,%3};"
        : "+f"(c0), "+f"(c1), "+f"(c2), "+f"(c3)
        : "r"(a0), "r"(a1), "r"(a2), "r"(a3), "r"(b0), "r"(b1));
}
__device__ __forceinline__ uint32_t pgqa_s2u(const void* p) {
    uint32_t a;
    asm("{ .reg .u64 t; cvta.to.shared.u64 t, %1; cvt.u32.u64 %0, t; }" : "=r"(a) : "l"(p));
    return a;
}
__device__ __forceinline__ void pgqa_cp16(uint32_t dst, const void* src) {
    asm volatile("cp.async.ca.shared.global [%0], [%1], 16;" :: "r"(dst), "l"(src));
}
__device__ __forceinline__ int pgqa_dperm(int w) { return (w < 4) ? 2 * w : 2 * w - 7; }

// ============== mma.sync tf32 GEMM body, cp.async double-buffered ============
// FUSE_NOISE: M tile is cp.async'd alongside A; per-chunk affine constants
// (c1, c2) fold the noise subtraction into the fragment load.
#define GAS 36
#define GBS 136
#define GA_SZ (128 * GAS)
#define GB_SZ (32 * GBS)
#define GSMEM_BYTES ((2 * GA_SZ + 2 * GB_SZ) * 4)
#define GSMEM_NOISE_BYTES ((2 * GA_SZ + 2 * GB_SZ + 2 * GA_SZ) * 4)

template<bool FUSE_NOISE, bool ROUND_OUT>
__device__ __forceinline__ void pgqa_gemm_body(
    const float* __restrict__ A, const float* __restrict__ B,
    const float* __restrict__ bias, float* __restrict__ C,
    int N, int K, float alpha, int m0, int col0, float* gsm, bool permQK) {
    float* Af0 = gsm;
    float* Bf0 = gsm + 2 * GA_SZ;
    float* Mf0 = gsm + 2 * GA_SZ + 2 * GB_SZ;   // only used if FUSE_NOISE
    const uint32_t sb = pgqa_s2u(gsm);
    const int t = threadIdx.x, warp = t >> 5, lane = t & 31;
    const int g = lane >> 2, q = lane & 3;
    const int wm = (warp >> 2) * 64, wn = (warp & 3) * 32;
    const int NC = K >> 5;

    float acc[4][4][4];
#pragma unroll
    for (int i = 0; i < 4; i++)
#pragma unroll
        for (int j = 0; j < 4; j++) {
            acc[i][j][0] = 0.f; acc[i][j][1] = 0.f;
            acc[i][j][2] = 0.f; acc[i][j][3] = 0.f;
        }

    auto issue_tile = [&](int c, int buf) {
        const int kc0 = c << 5;
#pragma unroll
        for (int i = 0; i < 4; i++) {
            int idx = t + (i << 8);
            int r = idx >> 3, j = (idx & 7) << 2;
            pgqa_cp16(sb + (uint32_t)(buf * GA_SZ + r * GAS + j) * 4,
                      A + (size_t)(m0 + r) * K + kc0 + j);
            if (FUSE_NOISE) {
                // M tile, same layout: row r -> M[hh][pp*64 + dd + j]
                const float* msrc = pgqa_M + ((size_t)(kc0 >> 6) << 16)
                                  + (size_t)((m0 + r) & (NP - 1)) * 64 + (kc0 & 63) + j;
                pgqa_cp16(sb + (uint32_t)((2 * GA_SZ + 2 * GB_SZ) + buf * GA_SZ
                                          + r * GAS + j) * 4, msrc);
            }
        }
#pragma unroll
        for (int i = 0; i < 4; i++) {
            int idx = t + (i << 8);
            int r = idx >> 5, j = (idx & 31) << 2;
            pgqa_cp16(sb + (uint32_t)(2 * GA_SZ + buf * GB_SZ + r * GBS + j) * 4,
                      B + (size_t)(kc0 + r) * N + col0 + j);
        }
    };

    issue_tile(0, 0);
    asm volatile("cp.async.commit_group;" ::: "memory");

    for (int c = 0; c < NC; ++c) {
        if (c + 1 < NC) {
            issue_tile(c + 1, (c + 1) & 1);
            asm volatile("cp.async.commit_group;" ::: "memory");
            asm volatile("cp.async.wait_group 1;" ::: "memory");
        } else {
            asm volatile("cp.async.wait_group 0;" ::: "memory");
        }
        __syncthreads();

        const float* Ab = Af0 + (c & 1) * GA_SZ;
        const float* Bb = Bf0 + (c & 1) * GB_SZ;
        const float* Mb = Mf0 + (c & 1) * GA_SZ;
        // per-chunk affine noise constants (uniform across CTA)
        float nc1 = 0.f, nc2 = 0.f;
        if (FUSE_NOISE) {
            int hh = (c << 5) >> 6;                  // head of this K-chunk
            int bh = (m0 >> 10) * NH + hh;           // whole CTA in one batch
            nc1 = pgqa_mistd[hh] * pgqa_rstd[bh];
            nc2 = pgqa_mmean[hh] * nc1 - pgqa_rmean[bh];
        }
#pragma unroll
        for (int k8 = 0; k8 < 32; k8 += 8) {
            unsigned a[4][4];
#pragma unroll
            for (int mt = 0; mt < 4; mt++) {
                const float* Ar = &Ab[(wm + mt * 16 + g) * GAS + k8 + q];
                if (FUSE_NOISE) {
                    const float* Mr = &Mb[(wm + mt * 16 + g) * GAS + k8 + q];
                    a[mt][0] = pgqa_tf32r(fmaf(-nc1, Mr[0], Ar[0]) + nc2);
                    a[mt][1] = pgqa_tf32r(fmaf(-nc1, Mr[8 * GAS], Ar[8 * GAS]) + nc2);
                    a[mt][2] = pgqa_tf32r(fmaf(-nc1, Mr[4], Ar[4]) + nc2);
                    a[mt][3] = pgqa_tf32r(fmaf(-nc1, Mr[8 * GAS + 4], Ar[8 * GAS + 4]) + nc2);
                } else {
                    a[mt][0] = pgqa_tf32r(Ar[0]);
                    a[mt][1] = pgqa_tf32r(Ar[8 * GAS]);
                    a[mt][2] = pgqa_tf32r(Ar[4]);
                    a[mt][3] = pgqa_tf32r(Ar[8 * GAS + 4]);
                }
            }
#pragma unroll
            for (int nt = 0; nt < 4; nt++) {
                const float* Br = &Bb[(k8 + q) * GBS + wn + nt * 8 + g];
                unsigned b0 = pgqa_tf32r(Br[0]);
                unsigned b1 = pgqa_tf32r(Br[4 * GBS]);
#pragma unroll
                for (int mt = 0; mt < 4; mt++)
                    pgqa_mma_tf32(acc[mt][nt][0], acc[mt][nt][1],
                                  acc[mt][nt][2], acc[mt][nt][3],
                                  a[mt][0], a[mt][1], a[mt][2], a[mt][3], b0, b1);
            }
        }
        __syncthreads();
    }

#pragma unroll
    for (int mt = 0; mt < 4; mt++) {
        int r0 = m0 + wm + mt * 16 + g;
#pragma unroll
        for (int nt = 0; nt < 4; nt++) {
            int c = col0 + wn + nt * 8 + q * 2;
            float v0 = acc[mt][nt][0] * alpha, v1 = acc[mt][nt][1] * alpha;
            float v2 = acc[mt][nt][2] * alpha, v3 = acc[mt][nt][3] * alpha;
            if (bias) { v0 += bias[c]; v1 += bias[c + 1]; v2 += bias[c]; v3 += bias[c + 1]; }
            if (ROUND_OUT) {
                v0 = __uint_as_float(pgqa_tf32r(v0));
                v1 = __uint_as_float(pgqa_tf32r(v1));
                v2 = __uint_as_float(pgqa_tf32r(v2));
                v3 = __uint_as_float(pgqa_tf32r(v3));
            }
            if (permQK) {
                int base = c & ~7, w = c & 7;
                int i0 = base | pgqa_dperm(w);
                int i1 = base | pgqa_dperm(w + 1);
                C[(size_t)r0 * N + i0] = v0;
                C[(size_t)r0 * N + i1] = v1;
                C[(size_t)(r0 + 8) * N + i0] = v2;
                C[(size_t)(r0 + 8) * N + i1] = v3;
            } else {
                *(float2*)(C + (size_t)r0 * N + c) = make_float2(v0, v1);
                *(float2*)(C + (size_t)(r0 + 8) * N + c) = make_float2(v2, v3);
            }
        }
    }
}

// ========== combined launch: blocks 0-95 generate M; 96.. do q/k/v ==========
__global__ __launch_bounds__(256)
void pgqa_qkv_mgen(const float* __restrict__ x,
                   const float* __restrict__ Wq, const float* __restrict__ Wk,
                   const float* __restrict__ Wv,
                   float* __restrict__ Qo, float* __restrict__ Ko,
                   float* __restrict__ Vo) {
    if (blockIdx.x < 96) {
        const int blk = blockIdx.x;
        const int h = blk >> 3, seg = blk & 7;
        const int tid = threadIdx.x;
        double s = 0.0, s2 = 0.0;
        for (unsigned k = tid; k < 8192; k += 256) {
            unsigned c = seg * 8192 + k;
            unsigned i = (unsigned)h * YLEN + c;
            float mv = pgqa_m_at(i);
            if (c == (unsigned)(h & 1)) mv = 0.f;
            pgqa_M[i] = mv;
            s += mv; s2 += (double)mv * mv;
        }
        __shared__ double shs[256], shs2[256];
        shs[tid] = s; shs2[tid] = s2; __syncthreads();
        for (int st = 128; st > 0; st >>= 1) {
            if (tid < st) { shs[tid] += shs[tid + st]; shs2[tid] += shs2[tid + st]; }
            __syncthreads();
        }
        if (tid == 0) { pgqa_msum[blk] = shs[0]; pgqa_msum2[blk] = shs2[0]; }
        return;
    }
    extern __shared__ float gsm[];
    const int bid = blockIdx.x - 96;
    const int cb = bid % 12, m0 = (bid / 12) * 128;
    const float* B; float* C; int N; int col0; float alpha; bool perm;
    if (cb < 6)      { B = Wq; C = Qo; N = PD;    col0 = cb * 128;       alpha = 0.125f * LOG2E; perm = true; }
    else if (cb < 9) { B = Wk; C = Ko; N = KVDIM; col0 = (cb - 6) * 128; alpha = 1.0f;           perm = true; }
    else             { B = Wv; C = Vo; N = KVDIM; col0 = (cb - 9) * 128; alpha = 1.0f;           perm = false; }
    pgqa_gemm_body<false, true>(x, B, nullptr, C, N, PD, alpha, m0, col0, gsm, perm);
}

__global__ __launch_bounds__(256)
void pgqa_proj_mma(const float* __restrict__ A, const float* __restrict__ B,
                   const float* __restrict__ bias, float* __restrict__ C) {
    extern __shared__ float gsm[];
    pgqa_gemm_body<true, false>(A, B, bias, C, PD, PD, 1.0f,
                                blockIdx.y * 128, blockIdx.x * 128, gsm, false);
}

// ============== mma.sync tf32 flash GQA attention ============================
#define KTS 72
#define VTS 72
#define PTS 72
#define KT_SZ (64 * KTS)
#define VT_SZ (64 * VTS)
#define ATTN_SMEM_BYTES ((2 * KT_SZ + VT_SZ + 128 * PTS) * 4)

__global__ __launch_bounds__(128, 2)
void pgqa_attn_mma(const float* __restrict__ Q, const float* __restrict__ K,
                   const float* __restrict__ V, float* __restrict__ Out) {
    extern __shared__ float atsm[];
    float* Kb0 = atsm;                         // 2 x [64][KTS]
    float* Vbf = atsm + 2 * KT_SZ;             // 1 x [64][VTS]
    unsigned* Ps = (unsigned*)(atsm + 2 * KT_SZ + VT_SZ);  // [128][PTS]
    const uint32_t sb = pgqa_s2u(atsm);

    const int t = threadIdx.x, warp = t >> 5, lane = t & 31;
    const int g = lane >> 2, qd = lane & 3;
    const int b = blockIdx.y / NKV, kvh = blockIdx.y % NKV;
    const int q0 = blockIdx.x * 64, wm = warp * 16;

    const float* Kg = K + (size_t)b * NP * KVDIM + kvh * HD;
    const float* Vg = V + (size_t)b * NP * KVDIM + kvh * HD;

    auto issue_k = [&](int tk, int buf) {
        int r = t >> 1, c0 = (t & 1) * 32;
        const float* ks = Kg + (size_t)(tk * 64 + r) * KVDIM + c0;
#pragma unroll
        for (int j = 0; j < 8; j++)
            pgqa_cp16(sb + (uint32_t)(buf * KT_SZ + r * KTS + c0 + j * 4) * 4, ks + j * 4);
    };
    auto issue_v = [&](int tk) {
        int r = t >> 1, c0 = (t & 1) * 32;
        const float* vs = Vg + (size_t)(tk * 64 + r) * KVDIM + c0;
#pragma unroll
        for (int j = 0; j < 8; j++)
            pgqa_cp16(sb + (uint32_t)(2 * KT_SZ + r * VTS + c0 + j * 4) * 4, vs + j * 4);
    };

    issue_k(0, 0);
    asm volatile("cp.async.commit_group;" ::: "memory");
    issue_v(0);
    asm volatile("cp.async.commit_group;" ::: "memory");

    {
        const float* src = Q + ((size_t)(b * NP + q0 + (t & 63))) * PD
                         + (kvh * 2 + (t >> 6)) * HD;
#pragma unroll
        for (int j = 0; j < 16; j++)
            *(uint4*)&Ps[t * PTS + j * 4] = *(const uint4*)(src + j * 4);
    }
    __syncthreads();

    unsigned qa0[8][4], qa1[8][4];
#pragma unroll
    for (int k8 = 0; k8 < 8; k8++) {
        uint2 a = *(const uint2*)&Ps[(wm + g) * PTS + k8 * 8 + 2 * qd];
        uint2 bb = *(const uint2*)&Ps[(wm + g + 8) * PTS + k8 * 8 + 2 * qd];
        qa0[k8][0] = a.x;  qa0[k8][2] = a.y;
        qa0[k8][1] = bb.x; qa0[k8][3] = bb.y;
        uint2 cc = *(const uint2*)&Ps[(64 + wm + g) * PTS + k8 * 8 + 2 * qd];
        uint2 dd = *(const uint2*)&Ps[(64 + wm + g + 8) * PTS + k8 * 8 + 2 * qd];
        qa1[k8][0] = cc.x; qa1[k8][2] = cc.y;
        qa1[k8][1] = dd.x; qa1[k8][3] = dd.y;
    }

    float o0[8][4], o1[8][4];
#pragma unroll
    for (int nt = 0; nt < 8; nt++) {
        o0[nt][0] = 0.f; o0[nt][1] = 0.f; o0[nt][2] = 0.f; o0[nt][3] = 0.f;
        o1[nt][0] = 0.f; o1[nt][1] = 0.f; o1[nt][2] = 0.f; o1[nt][3] = 0.f;
    }
    float mrA = -1e30f, mrB = -1e30f, mrC = -1e30f, mrD = -1e30f;
    float lrA = 0.f, lrB = 0.f, lrC = 0.f, lrD = 0.f;

    const int NT = NP / 64;
    for (int tk = 0; tk < NT; tk++) {
        if (tk + 1 < NT) {
            issue_k(tk + 1, (tk + 1) & 1);
            asm volatile("cp.async.commit_group;" ::: "memory");
            asm volatile("cp.async.wait_group 1;" ::: "memory");
        } else {
            asm volatile("cp.async.wait_group 0;" ::: "memory");
        }
        __syncthreads();
        const unsigned* Kb = (const unsigned*)(Kb0 + (tk & 1) * KT_SZ);
        const unsigned* Vb = (const unsigned*)Vbf;

        float s0[8][4], s1[8][4];
#pragma unroll
        for (int nt = 0; nt < 8; nt++) {
            s0[nt][0] = 0.f; s0[nt][1] = 0.f; s0[nt][2] = 0.f; s0[nt][3] = 0.f;
            s1[nt][0] = 0.f; s1[nt][1] = 0.f; s1[nt][2] = 0.f; s1[nt][3] = 0.f;
        }
#pragma unroll
        for (int nt = 0; nt < 8; nt++) {
            const unsigned* Kr = &Kb[(nt * 8 + g) * KTS];
#pragma unroll
            for (int k8 = 0; k8 < 8; k8++) {
                uint2 bb = *(const uint2*)&Kr[k8 * 8 + 2 * qd];
                pgqa_mma_tf32(s0[nt][0], s0[nt][1], s0[nt][2], s0[nt][3],
                              qa0[k8][0], qa0[k8][1], qa0[k8][2], qa0[k8][3], bb.x, bb.y);
                pgqa_mma_tf32(s1[nt][0], s1[nt][1], s1[nt][2], s1[nt][3],
                              qa1[k8][0], qa1[k8][1], qa1[k8][2], qa1[k8][3], bb.x, bb.y);
            }
        }

        float mxA = fmaxf(s0[0][0], s0[0][1]), mxB = fmaxf(s0[0][2], s0[0][3]);
        float mxC = fmaxf(s1[0][0], s1[0][1]), mxD = fmaxf(s1[0][2], s1[0][3]);
#pragma unroll
        for (int nt = 1; nt < 8; nt++) {
            mxA = fmaxf(mxA, fmaxf(s0[nt][0], s0[nt][1]));
            mxB = fmaxf(mxB, fmaxf(s0[nt][2], s0[nt][3]));
            mxC = fmaxf(mxC, fmaxf(s1[nt][0], s1[nt][1]));
            mxD = fmaxf(mxD, fmaxf(s1[nt][2], s1[nt][3]));
        }
        mxA = fmaxf(mxA, __shfl_xor_sync(~0u, mxA, 1));
        mxA = fmaxf(mxA, __shfl_xor_sync(~0u, mxA, 2));
        mxB = fmaxf(mxB, __shfl_xor_sync(~0u, mxB, 1));
        mxB = fmaxf(mxB, __shfl_xor_sync(~0u, mxB, 2));
        mxC = fmaxf(mxC, __shfl_xor_sync(~0u, mxC, 1));
        mxC = fmaxf(mxC, __shfl_xor_sync(~0u, mxC, 2));
        mxD = fmaxf(mxD, __shfl_xor_sync(~0u, mxD, 1));
        mxD = fmaxf(mxD, __shfl_xor_sync(~0u, mxD, 2));
        float mnA = fmaxf(mrA, mxA), mnB = fmaxf(mrB, mxB);
        float mnC = fmaxf(mrC, mxC), mnD = fmaxf(mrD, mxD);
        float cA = exp2f(mrA - mnA), cB = exp2f(mrB - mnB);
        float cC = exp2f(mrC - mnC), cD = exp2f(mrD - mnD);
        float sA = 0.f, sB = 0.f, sC = 0.f, sD = 0.f;
#pragma unroll
        for (int nt = 0; nt < 8; nt++) {
            float p00 = exp2f(s0[nt][0] - mnA), p01 = exp2f(s0[nt][1] - mnA);
            float p02 = exp2f(s0[nt][2] - mnB), p03 = exp2f(s0[nt][3] - mnB);
            float p10 = exp2f(s1[nt][0] - mnC), p11 = exp2f(s1[nt][1] - mnC);
            float p12 = exp2f(s1[nt][2] - mnD), p13 = exp2f(s1[nt][3] - mnD);
            sA += p00 + p01; sB += p02 + p03; sC += p10 + p11; sD += p12 + p13;
            *(uint2*)&Ps[(wm + g) * PTS + nt * 8 + 2 * qd] =
                make_uint2(pgqa_tf32r(p00), pgqa_tf32r(p01));
            *(uint2*)&Ps[(wm + g + 8) * PTS + nt * 8 + 2 * qd] =
                make_uint2(pgqa_tf32r(p02), pgqa_tf32r(p03));
            *(uint2*)&Ps[(64 + wm + g) * PTS + nt * 8 + 2 * qd] =
                make_uint2(pgqa_tf32r(p10), pgqa_tf32r(p11));
            *(uint2*)&Ps[(64 + wm + g + 8) * PTS + nt * 8 + 2 * qd] =
                make_uint2(pgqa_tf32r(p12), pgqa_tf32r(p13));
            o0[nt][0] *= cA; o0[nt][1] *= cA; o0[nt][2] *= cB; o0[nt][3] *= cB;
            o1[nt][0] *= cC; o1[nt][1] *= cC; o1[nt][2] *= cD; o1[nt][3] *= cD;
        }
        sA += __shfl_xor_sync(~0u, sA, 1); sA += __shfl_xor_sync(~0u, sA, 2);
        sB += __shfl_xor_sync(~0u, sB, 1); sB += __shfl_xor_sync(~0u, sB, 2);
        sC += __shfl_xor_sync(~0u, sC, 1); sC += __shfl_xor_sync(~0u, sC, 2);
        sD += __shfl_xor_sync(~0u, sD, 1); sD += __shfl_xor_sync(~0u, sD, 2);
        lrA = lrA * cA + sA; lrB = lrB * cB + sB;
        lrC = lrC * cC + sC; lrD = lrD * cD + sD;
        mrA = mnA; mrB = mnB; mrC = mnC; mrD = mnD;
        __syncwarp();

#pragma unroll
        for (int k8 = 0; k8 < 8; k8++) {
            unsigned pa00 = Ps[(wm + g) * PTS + k8 * 8 + qd];
            unsigned pa01 = Ps[(wm + g + 8) * PTS + k8 * 8 + qd];
            unsigned pa02 = Ps[(wm + g) * PTS + k8 * 8 + qd + 4];
            unsigned pa03 = Ps[(wm + g + 8) * PTS + k8 * 8 + qd + 4];
            unsigned pa10 = Ps[(64 + wm + g) * PTS + k8 * 8 + qd];
            unsigned pa11 = Ps[(64 + wm + g + 8) * PTS + k8 * 8 + qd];
            unsigned pa12 = Ps[(64 + wm + g) * PTS + k8 * 8 + qd + 4];
            unsigned pa13 = Ps[(64 + wm + g + 8) * PTS + k8 * 8 + qd + 4];
            const unsigned* Vk0 = &Vb[(k8 * 8 + qd) * VTS];
            const unsigned* Vk1 = &Vb[(k8 * 8 + qd + 4) * VTS];
#pragma unroll
            for (int nt = 0; nt < 8; nt++) {
                unsigned b0 = Vk0[nt * 8 + g];
                unsigned b1 = Vk1[nt * 8 + g];
                pgqa_mma_tf32(o0[nt][0], o0[nt][1], o0[nt][2], o0[nt][3],
                              pa00, pa01, pa02, pa03, b0, b1);
                pgqa_mma_tf32(o1[nt][0], o1[nt][1], o1[nt][2], o1[nt][3],
                              pa10, pa11, pa12, pa13, b0, b1);
            }
        }
        __syncthreads();
        if (tk + 1 < NT) {
            issue_v(tk + 1);
            asm volatile("cp.async.commit_group;" ::: "memory");
        }
    }

    float iA = 1.f / lrA, iB = 1.f / lrB, iC = 1.f / lrC, iD = 1.f / lrD;
    const int h0 = kvh * 2, h1 = kvh * 2 + 1;
    float* OA = Out + ((size_t)(b * NP + q0 + wm + g)) * PD;
    float* OB = Out + ((size_t)(b * NP + q0 + wm + g + 8)) * PD;
    double sh0 = 0.0, sq0 = 0.0, sh1 = 0.0, sq1 = 0.0;
#pragma unroll
    for (int nt = 0; nt < 8; nt++) {
        int c = nt * 8 + qd * 2;
        float a0 = o0[nt][0] * iA, a1 = o0[nt][1] * iA;
        float b0v = o0[nt][2] * iB, b1v = o0[nt][3] * iB;
        float c0v = o1[nt][0] * iC, c1v = o1[nt][1] * iC;
        float d0v = o1[nt][2] * iD, d1v = o1[nt][3] * iD;
        *(float2*)(OA + h0 * HD + c) = make_float2(a0, a1);
        *(float2*)(OB + h0 * HD + c) = make_float2(b0v, b1v);
        *(float2*)(OA + h1 * HD + c) = make_float2(c0v, c1v);
        *(float2*)(OB + h1 * HD + c) = make_float2(d0v, d1v);
        sh0 += (double)a0 + a1 + b0v + b1v;
        sq0 += (double)a0 * a0 + (double)a1 * a1 + (double)b0v * b0v + (double)b1v * b1v;
        sh1 += (double)c0v + c1v + d0v + d1v;
        sq1 += (double)c0v * c0v + (double)c1v * c1v + (double)d0v * d0v + (double)d1v * d1v;
    }
    double* dsc = (double*)atsm;
    __syncthreads();
    dsc[t] = sh0; dsc[128 + t] = sq0; dsc[256 + t] = sh1; dsc[384 + t] = sq1;
    __syncthreads();
    for (int st = 64; st > 0; st >>= 1) {
        if (t < st) {
            dsc[t] += dsc[t + st];
            dsc[128 + t] += dsc[128 + t + st];
            dsc[256 + t] += dsc[256 + t + st];
            dsc[384 + t] += dsc[384 + t + st];
        }
        __syncthreads();
    }
    if (t == 0) {
        int bh0 = b * NH + h0, bh1 = b * NH + h1, qt = blockIdx.x;
        pgqa_rsum[bh0 * 16 + qt] = dsc[0];
        pgqa_rsum2[bh0 * 16 + qt] = dsc[128];
        pgqa_rsum[bh1 * 16 + qt] = dsc[256];
        pgqa_rsum2[bh1 * 16 + qt] = dsc[384];
    }
}

// -------- finalize both stat sets (M stats + per-(b,h) row stats) ------------
__global__ void pgqa_sfin() {
    int tid = threadIdx.x;   // 96
    if (tid < NH) {
        double sm = 0.0, sm2 = 0.0;
#pragma unroll
        for (int s = 0; s < 8; s++) { sm += pgqa_msum[tid * 8 + s]; sm2 += pgqa_msum2[tid * 8 + s]; }
        double n = (double)YLEN;
        double mean = sm / n;
        double var = (sm2 - sm * sm / n) / (n - 1.0);
        double sd = sqrt(var > 0.0 ? var : 0.0);
        if (sd == 0.0) sd = 1.0;
        pgqa_mmean[tid] = (float)mean;
        pgqa_mistd[tid] = (float)(1.0 / sd);
    }
    if (tid < NB * NH) {
        double sm = 0.0, sm2 = 0.0;
#pragma unroll
        for (int s = 0; s < 16; s++) { sm += pgqa_rsum[tid * 16 + s]; sm2 += pgqa_rsum2[tid * 16 + s]; }
        double n = (double)YLEN;
        double mean = sm / n;
        double var = (sm2 - sm * sm / n) / (n - 1.0);
        pgqa_rmean[tid] = (float)mean;
        pgqa_rstd[tid] = (float)sqrt(var > 0.0 ? var : 0.0);
    }
}

// ---------------- launcher ---------------------------------------------------
extern "C" void kernel_launch(void* const* d_in, const int* in_sizes, int n_in,
                              void* d_out, int out_size) {
    const float* x  = (const float*)d_in[0];
    const float* Wq = (const float*)d_in[1];
    const float* Wk = (const float*)d_in[2];
    const float* Wv = (const float*)d_in[3];
    const float* Wp = (const float*)d_in[4];
    const float* bp = (const float*)d_in[5];
    float* out = (float*)d_out;

    float *Qb, *Kb, *Vb, *Ab;
    cudaGetSymbolAddress((void**)&Qb, pgqa_Q);
    cudaGetSymbolAddress((void**)&Kb, pgqa_K);
    cudaGetSymbolAddress((void**)&Vb, pgqa_V);
    cudaGetSymbolAddress((void**)&Ab, pgqa_Att);

    cudaFuncSetAttribute(pgqa_attn_mma, cudaFuncAttributeMaxDynamicSharedMemorySize, ATTN_SMEM_BYTES);
    cudaFuncSetAttribute(pgqa_qkv_mgen, cudaFuncAttributeMaxDynamicSharedMemorySize, GSMEM_BYTES);
    cudaFuncSetAttribute(pgqa_proj_mma, cudaFuncAttributeMaxDynamicSharedMemorySize, GSMEM_NOISE_BYTES);

    // M gen/stats (blocks 0-95) + fused q/k/v projections (blocks 96-863)
    pgqa_qkv_mgen<<<96 + 12 * (BPROWS / 128), 256, GSMEM_BYTES>>>(
        x, Wq, Wk, Wv, Qb, Kb, Vb);

    // flash attention (with fused per-(b,h) output stat partials)
    pgqa_attn_mma<<<dim3(NP / 64, NB * NKV), 128, ATTN_SMEM_BYTES>>>(Qb, Kb, Vb, Ab);

    // finalize M stats + row stats
    pgqa_sfin<<<1, 96>>>();

    // output projection (+bias) with affine noise subtraction in A-frag load
    pgqa_proj_mma<<<dim3(PD / 128, BPROWS / 128), 256, GSMEM_NOISE_BYTES>>>(
        Ab, Wp, bp, out);
}

// round 16
// speedup vs baseline: 1.0766x; 1.0766x over previous
#include <cuda_runtime.h>
#include <math.h>
#include <stdint.h>

// Problem constants
#define PD   768
#define NB   8
#define NP   1024
#define NH   12
#define NKV  6
#define HD   64
#define BPROWS (NB*NP)          // 8192
#define KVDIM  (NKV*HD)         // 384
#define YLEN   (NP*HD)          // 65536
#define MTOT   (NH*YLEN)        // 786432
#define LOG2E  1.44269504088896340736f

// ---------------- scratch (static device memory; no allocations) -------------
__device__ float pgqa_Xr[BPROWS*PD];     // tf32-rounded x
__device__ float pgqa_Wqr[PD*PD];        // tf32-rounded weights
__device__ float pgqa_Wkr[PD*KVDIM];
__device__ float pgqa_Wvr[PD*KVDIM];
__device__ float pgqa_Wpr[PD*PD];
__device__ float pgqa_Q[BPROWS*PD];      // q*(log2e/8), tf32-rounded, d-permuted
__device__ float pgqa_K[BPROWS*KVDIM];   // tf32-rounded, d-permuted
__device__ float pgqa_V[BPROWS*KVDIM];   // tf32-rounded
__device__ float pgqa_Att[BPROWS*PD];    // attention out
__device__ float pgqa_X2[BPROWS*PD];     // noise-subtracted att, tf32-rounded
__device__ float pgqa_M[MTOT];           // uniform matrix [12, 65536]
__device__ float pgqa_rmean[NB*NH];
__device__ float pgqa_rstd[NB*NH];
__device__ float pgqa_mmean[NH];
__device__ float pgqa_mistd[NH];
__device__ double pgqa_msum[96];
__device__ double pgqa_msum2[96];
__device__ double pgqa_rsum[NB*NH*16];
__device__ double pgqa_rsum2[NB*NH*16];

// ---------------- JAX threefry2x32, key = (0, 42) ----------------------------
__device__ __forceinline__ void pgqa_threefry(unsigned x0, unsigned x1,
                                              unsigned& o0, unsigned& o1) {
    const unsigned ks0 = 0u, ks1 = 42u, ks2 = 0x1BD11BDAu ^ 42u;
    x0 += ks0; x1 += ks1;
#define PGQA_R(r) { x0 += x1; x1 = (x1 << (r)) | (x1 >> (32 - (r))); x1 ^= x0; }
    PGQA_R(13) PGQA_R(15) PGQA_R(26) PGQA_R(6)
    x0 += ks1; x1 += ks2 + 1u;
    PGQA_R(17) PGQA_R(29) PGQA_R(16) PGQA_R(24)
    x0 += ks2; x1 += ks0 + 2u;
    PGQA_R(13) PGQA_R(15) PGQA_R(26) PGQA_R(6)
    x0 += ks0; x1 += ks1 + 3u;
    PGQA_R(17) PGQA_R(29) PGQA_R(16) PGQA_R(24)
    x0 += ks1; x1 += ks2 + 4u;
    PGQA_R(13) PGQA_R(15) PGQA_R(26) PGQA_R(6)
    x0 += ks2; x1 += ks0 + 5u;
#undef PGQA_R
    o0 = x0; o1 = x1;
}
__device__ __forceinline__ float pgqa_uniform(unsigned bits) {
    return __uint_as_float((bits >> 9) | 0x3f800000u) - 1.0f;
}
__device__ __forceinline__ float pgqa_m_at(unsigned i) {
    unsigned o0, o1;
    pgqa_threefry(0u, i, o0, o1);
    return pgqa_uniform(o0 ^ o1);
}

__device__ __forceinline__ unsigned pgqa_tf32r(float f) {
    unsigned u; asm("cvt.rna.tf32.f32 %0, %1;" : "=r"(u) : "f"(f)); return u;
}
__device__ __forceinline__ float pgqa_tf32f(float f) {
    return __uint_as_float(pgqa_tf32r(f));
}
__device__ __forceinline__ void pgqa_mma_tf32(float& c0, float& c1, float& c2, float& c3,
                                              unsigned a0, unsigned a1, unsigned a2, unsigned a3,
                                              unsigned b0, unsigned b1) {
    asm volatile(
        "mma.sync.aligned.m16n8k8.row.col.f32.tf32.tf32.f32 "
        "{%0,%1,%2,%3}, {%4,%5,%6,%7}, {%8,%9}, {%0,%1,%2,%3};"
        : "+f"(c0), "+f"(c1), "+f"(c2), "+f"(c3)
        : "r"(a0), "r"(a1), "r"(a2), "r"(a3), "r"(b0), "r"(b1));
}
__device__ __forceinline__ uint32_t pgqa_s2u(const void* p) {
    uint32_t a;
    asm("{ .reg .u64 t; cvta.to.shared.u64 t, %1; cvt.u32.u64 %0, t; }" : "=r"(a) : "l"(p));
    return a;
}
__device__ __forceinline__ void pgqa_cp16(uint32_t dst, const void* src) {
    asm volatile("cp.async.ca.shared.global [%0], [%1], 16;" :: "r"(dst), "l"(src));
}
__device__ __forceinline__ int pgqa_dperm(int w) { return (w < 4) ? 2 * w : 2 * w - 7; }

// ---------------- prep: round x and weights to tf32 bits ---------------------
#define XN4   (BPROWS * PD / 4)        // 1572864
#define WQ4   (PD * PD / 4)            // 147456
#define WK4   (PD * KVDIM / 4)         // 73728
__global__ void pgqa_prep(const float* __restrict__ x,  const float* __restrict__ Wq,
                          const float* __restrict__ Wk, const float* __restrict__ Wv,
                          const float* __restrict__ Wp) {
    const size_t total = XN4 + WQ4 + 2 * WK4 + WQ4;
    for (size_t i = (size_t)blockIdx.x * blockDim.x + threadIdx.x; i < total;
         i += (size_t)gridDim.x * blockDim.x) {
        const float4* src; float4* dst; size_t j = i;
        if (j < XN4) { src = (const float4*)x; dst = (float4*)pgqa_Xr; }
        else if ((j -= XN4) < WQ4) { src = (const float4*)Wq; dst = (float4*)pgqa_Wqr; }
        else if ((j -= WQ4) < WK4) { src = (const float4*)Wk; dst = (float4*)pgqa_Wkr; }
        else if ((j -= WK4) < WK4) { src = (const float4*)Wv; dst = (float4*)pgqa_Wvr; }
        else { j -= WK4; src = (const float4*)Wp; dst = (float4*)pgqa_Wpr; }
        float4 v = src[j];
        v.x = pgqa_tf32f(v.x); v.y = pgqa_tf32f(v.y);
        v.z = pgqa_tf32f(v.z); v.w = pgqa_tf32f(v.w);
        dst[j] = v;
    }
}

// ============== mma.sync tf32 GEMM body: raw tf32 bits, no cvt ===============
#define GAS 36
#define GBS 136
#define GA_SZ (128 * GAS)
#define GB_SZ (32 * GBS)
#define GSMEM_BYTES ((2 * GA_SZ + 2 * GB_SZ) * 4)

template<bool ROUND_OUT>
__device__ __forceinline__ void pgqa_gemm_body(
    const float* __restrict__ A, const float* __restrict__ B,
    const float* __restrict__ bias, float* __restrict__ C,
    int N, int K, float alpha, int m0, int col0, float* gsm, bool permQK) {
    float* Af0 = gsm;
    float* Bf0 = gsm + 2 * GA_SZ;
    const uint32_t sb = pgqa_s2u(gsm);
    const int t = threadIdx.x, warp = t >> 5, lane = t & 31;
    const int g = lane >> 2, q = lane & 3;
    const int wm = (warp >> 2) * 64, wn = (warp & 3) * 32;
    const int NC = K >> 5;

    float acc[4][4][4];
#pragma unroll
    for (int i = 0; i < 4; i++)
#pragma unroll
        for (int j = 0; j < 4; j++) {
            acc[i][j][0] = 0.f; acc[i][j][1] = 0.f;
            acc[i][j][2] = 0.f; acc[i][j][3] = 0.f;
        }

    auto issue_tile = [&](int c, int buf) {
        const int kc0 = c << 5;
#pragma unroll
        for (int i = 0; i < 4; i++) {
            int idx = t + (i << 8);
            int r = idx >> 3, j = (idx & 7) << 2;
            pgqa_cp16(sb + (uint32_t)(buf * GA_SZ + r * GAS + j) * 4,
                      A + (size_t)(m0 + r) * K + kc0 + j);
        }
#pragma unroll
        for (int i = 0; i < 4; i++) {
            int idx = t + (i << 8);
            int r = idx >> 5, j = (idx & 31) << 2;
            pgqa_cp16(sb + (uint32_t)(2 * GA_SZ + buf * GB_SZ + r * GBS + j) * 4,
                      B + (size_t)(kc0 + r) * N + col0 + j);
        }
    };

    issue_tile(0, 0);
    asm volatile("cp.async.commit_group;" ::: "memory");

    for (int c = 0; c < NC; ++c) {
        if (c + 1 < NC) {
            issue_tile(c + 1, (c + 1) & 1);
            asm volatile("cp.async.commit_group;" ::: "memory");
            asm volatile("cp.async.wait_group 1;" ::: "memory");
        } else {
            asm volatile("cp.async.wait_group 0;" ::: "memory");
        }
        __syncthreads();

        const unsigned* Ab = (const unsigned*)(Af0 + (c & 1) * GA_SZ);
        const unsigned* Bb = (const unsigned*)(Bf0 + (c & 1) * GB_SZ);
#pragma unroll
        for (int k8 = 0; k8 < 32; k8 += 8) {
            unsigned a[4][4];
#pragma unroll
            for (int mt = 0; mt < 4; mt++) {
                const unsigned* Ar = &Ab[(wm + mt * 16 + g) * GAS + k8 + q];
                a[mt][0] = Ar[0];
                a[mt][1] = Ar[8 * GAS];
                a[mt][2] = Ar[4];
                a[mt][3] = Ar[8 * GAS + 4];
            }
#pragma unroll
            for (int nt = 0; nt < 4; nt++) {
                const unsigned* Br = &Bb[(k8 + q) * GBS + wn + nt * 8 + g];
                unsigned b0 = Br[0];
                unsigned b1 = Br[4 * GBS];
#pragma unroll
                for (int mt = 0; mt < 4; mt++)
                    pgqa_mma_tf32(acc[mt][nt][0], acc[mt][nt][1],
                                  acc[mt][nt][2], acc[mt][nt][3],
                                  a[mt][0], a[mt][1], a[mt][2], a[mt][3], b0, b1);
            }
        }
        __syncthreads();
    }

#pragma unroll
    for (int mt = 0; mt < 4; mt++) {
        int r0 = m0 + wm + mt * 16 + g;
#pragma unroll
        for (int nt = 0; nt < 4; nt++) {
            int c = col0 + wn + nt * 8 + q * 2;
            float v0 = acc[mt][nt][0] * alpha, v1 = acc[mt][nt][1] * alpha;
            float v2 = acc[mt][nt][2] * alpha, v3 = acc[mt][nt][3] * alpha;
            if (bias) { v0 += bias[c]; v1 += bias[c + 1]; v2 += bias[c]; v3 += bias[c + 1]; }
            if (ROUND_OUT) {
                v0 = pgqa_tf32f(v0); v1 = pgqa_tf32f(v1);
                v2 = pgqa_tf32f(v2); v3 = pgqa_tf32f(v3);
            }
            if (permQK) {
                int base = c & ~7, w = c & 7;
                int i0 = base | pgqa_dperm(w);
                int i1 = base | pgqa_dperm(w + 1);
                C[(size_t)r0 * N + i0] = v0;
                C[(size_t)r0 * N + i1] = v1;
                C[(size_t)(r0 + 8) * N + i0] = v2;
                C[(size_t)(r0 + 8) * N + i1] = v3;
            } else {
                *(float2*)(C + (size_t)r0 * N + c) = make_float2(v0, v1);
                *(float2*)(C + (size_t)(r0 + 8) * N + c) = make_float2(v2, v3);
            }
        }
    }
}

// ========== combined launch: blocks 0-95 generate M; 96.. do q/k/v ==========
__global__ __launch_bounds__(256)
void pgqa_qkv_mgen(float* __restrict__ Qo, float* __restrict__ Ko,
                   float* __restrict__ Vo) {
    if (blockIdx.x < 96) {
        const int blk = blockIdx.x;
        const int h = blk >> 3, seg = blk & 7;
        const int tid = threadIdx.x;
        double s = 0.0, s2 = 0.0;
        for (unsigned k = tid; k < 8192; k += 256) {
            unsigned c = seg * 8192 + k;
            unsigned i = (unsigned)h * YLEN + c;
            float mv = pgqa_m_at(i);
            if (c == (unsigned)(h & 1)) mv = 0.f;
            pgqa_M[i] = mv;
            s += mv; s2 += (double)mv * mv;
        }
        __shared__ double shs[256], shs2[256];
        shs[tid] = s; shs2[tid] = s2; __syncthreads();
        for (int st = 128; st > 0; st >>= 1) {
            if (tid < st) { shs[tid] += shs[tid + st]; shs2[tid] += shs2[tid + st]; }
            __syncthreads();
        }
        if (tid == 0) { pgqa_msum[blk] = shs[0]; pgqa_msum2[blk] = shs2[0]; }
        return;
    }
    extern __shared__ float gsm[];
    const int bid = blockIdx.x - 96;
    const int cb = bid % 12, m0 = (bid / 12) * 128;
    const float* B; float* C; int N; int col0; float alpha; bool perm;
    if (cb < 6)      { B = pgqa_Wqr; C = Qo; N = PD;    col0 = cb * 128;       alpha = 0.125f * LOG2E; perm = true; }
    else if (cb < 9) { B = pgqa_Wkr; C = Ko; N = KVDIM; col0 = (cb - 6) * 128; alpha = 1.0f;           perm = true; }
    else             { B = pgqa_Wvr; C = Vo; N = KVDIM; col0 = (cb - 9) * 128; alpha = 1.0f;           perm = false; }
    pgqa_gemm_body<true>(pgqa_Xr, B, nullptr, C, N, PD, alpha, m0, col0, gsm, perm);
}

__global__ __launch_bounds__(256)
void pgqa_proj_mma(const float* __restrict__ bias, float* __restrict__ C) {
    extern __shared__ float gsm[];
    pgqa_gemm_body<false>(pgqa_X2, pgqa_Wpr, bias, C, PD, PD, 1.0f,
                          blockIdx.y * 128, blockIdx.x * 128, gsm, false);
}

// -------- noise subtraction, tf32-pre-rounded output -------------------------
__global__ void pgqa_noise(const float* __restrict__ Att) {
    size_t i = (size_t)blockIdx.x * 256 + threadIdx.x;   // over float4s
    int col4 = (int)(i % (PD / 4));
    size_t row = i / (PD / 4);
    int j = col4 * 4;
    int hh = j >> 6;
    int bh = (int)(row >> 10) * NH + hh;
    float c1 = pgqa_mistd[hh] * pgqa_rstd[bh];
    float c2 = pgqa_mmean[hh] * c1 - pgqa_rmean[bh];
    float4 m = *(const float4*)(pgqa_M + ((size_t)hh << 16)
                                + (size_t)(row & (NP - 1)) * 64 + (j & 63));
    float4 v = ((const float4*)Att)[i];
    v.x = pgqa_tf32f(fmaf(-c1, m.x, v.x) + c2);
    v.y = pgqa_tf32f(fmaf(-c1, m.y, v.y) + c2);
    v.z = pgqa_tf32f(fmaf(-c1, m.z, v.z) + c2);
    v.w = pgqa_tf32f(fmaf(-c1, m.w, v.w) + c2);
    ((float4*)pgqa_X2)[i] = v;
}

// ============== mma.sync tf32 flash GQA attention ============================
#define KTS 72
#define VTS 72
#define PTS 72
#define KT_SZ (64 * KTS)
#define VT_SZ (64 * VTS)
#define ATTN_SMEM_BYTES ((2 * KT_SZ + VT_SZ + 128 * PTS) * 4)

__global__ __launch_bounds__(128, 2)
void pgqa_attn_mma(const float* __restrict__ Q, const float* __restrict__ K,
                   const float* __restrict__ V, float* __restrict__ Out) {
    extern __shared__ float atsm[];
    float* Kb0 = atsm;                         // 2 x [64][KTS]
    float* Vbf = atsm + 2 * KT_SZ;             // 1 x [64][VTS]
    unsigned* Ps = (unsigned*)(atsm + 2 * KT_SZ + VT_SZ);  // [128][PTS]
    const uint32_t sb = pgqa_s2u(atsm);

    const int t = threadIdx.x, warp = t >> 5, lane = t & 31;
    const int g = lane >> 2, qd = lane & 3;
    const int b = blockIdx.y / NKV, kvh = blockIdx.y % NKV;
    const int q0 = blockIdx.x * 64, wm = warp * 16;

    const float* Kg = K + (size_t)b * NP * KVDIM + kvh * HD;
    const float* Vg = V + (size_t)b * NP * KVDIM + kvh * HD;

    auto issue_k = [&](int tk, int buf) {
        int r = t >> 1, c0 = (t & 1) * 32;
        const float* ks = Kg + (size_t)(tk * 64 + r) * KVDIM + c0;
#pragma unroll
        for (int j = 0; j < 8; j++)
            pgqa_cp16(sb + (uint32_t)(buf * KT_SZ + r * KTS + c0 + j * 4) * 4, ks + j * 4);
    };
    auto issue_v = [&](int tk) {
        int r = t >> 1, c0 = (t & 1) * 32;
        const float* vs = Vg + (size_t)(tk * 64 + r) * KVDIM + c0;
#pragma unroll
        for (int j = 0; j < 8; j++)
            pgqa_cp16(sb + (uint32_t)(2 * KT_SZ + r * VTS + c0 + j * 4) * 4, vs + j * 4);
    };

    issue_k(0, 0);
    asm volatile("cp.async.commit_group;" ::: "memory");
    issue_v(0);
    asm volatile("cp.async.commit_group;" ::: "memory");

    {
        const float* src = Q + ((size_t)(b * NP + q0 + (t & 63))) * PD
                         + (kvh * 2 + (t >> 6)) * HD;
#pragma unroll
        for (int j = 0; j < 16; j++)
            *(uint4*)&Ps[t * PTS + j * 4] = *(const uint4*)(src + j * 4);
    }
    __syncthreads();

    unsigned qa0[8][4], qa1[8][4];
#pragma unroll
    for (int k8 = 0; k8 < 8; k8++) {
        uint2 a = *(const uint2*)&Ps[(wm + g) * PTS + k8 * 8 + 2 * qd];
        uint2 bb = *(const uint2*)&Ps[(wm + g + 8) * PTS + k8 * 8 + 2 * qd];
        qa0[k8][0] = a.x;  qa0[k8][2] = a.y;
        qa0[k8][1] = bb.x; qa0[k8][3] = bb.y;
        uint2 cc = *(const uint2*)&Ps[(64 + wm + g) * PTS + k8 * 8 + 2 * qd];
        uint2 dd = *(const uint2*)&Ps[(64 + wm + g + 8) * PTS + k8 * 8 + 2 * qd];
        qa1[k8][0] = cc.x; qa1[k8][2] = cc.y;
        qa1[k8][1] = dd.x; qa1[k8][3] = dd.y;
    }

    float o0[8][4], o1[8][4];
#pragma unroll
    for (int nt = 0; nt < 8; nt++) {
        o0[nt][0] = 0.f; o0[nt][1] = 0.f; o0[nt][2] = 0.f; o0[nt][3] = 0.f;
        o1[nt][0] = 0.f; o1[nt][1] = 0.f; o1[nt][2] = 0.f; o1[nt][3] = 0.f;
    }
    float mrA = -1e30f, mrB = -1e30f, mrC = -1e30f, mrD = -1e30f;
    float lrA = 0.f, lrB = 0.f, lrC = 0.f, lrD = 0.f;

    const int NT = NP / 64;
    for (int tk = 0; tk < NT; tk++) {
        if (tk + 1 < NT) {
            issue_k(tk + 1, (tk + 1) & 1);
            asm volatile("cp.async.commit_group;" ::: "memory");
            asm volatile("cp.async.wait_group 1;" ::: "memory");
        } else {
            asm volatile("cp.async.wait_group 0;" ::: "memory");
        }
        __syncthreads();
        const unsigned* Kb = (const unsigned*)(Kb0 + (tk & 1) * KT_SZ);
        const unsigned* Vb = (const unsigned*)Vbf;

        float s0[8][4], s1[8][4];
#pragma unroll
        for (int nt = 0; nt < 8; nt++) {
            s0[nt][0] = 0.f; s0[nt][1] = 0.f; s0[nt][2] = 0.f; s0[nt][3] = 0.f;
            s1[nt][0] = 0.f; s1[nt][1] = 0.f; s1[nt][2] = 0.f; s1[nt][3] = 0.f;
        }
#pragma unroll
        for (int nt = 0; nt < 8; nt++) {
            const unsigned* Kr = &Kb[(nt * 8 + g) * KTS];
#pragma unroll
            for (int k8 = 0; k8 < 8; k8++) {
                uint2 bb = *(const uint2*)&Kr[k8 * 8 + 2 * qd];
                pgqa_mma_tf32(s0[nt][0], s0[nt][1], s0[nt][2], s0[nt][3],
                              qa0[k8][0], qa0[k8][1], qa0[k8][2], qa0[k8][3], bb.x, bb.y);
                pgqa_mma_tf32(s1[nt][0], s1[nt][1], s1[nt][2], s1[nt][3],
                              qa1[k8][0], qa1[k8][1], qa1[k8][2], qa1[k8][3], bb.x, bb.y);
            }
        }

        float mxA = fmaxf(s0[0][0], s0[0][1]), mxB = fmaxf(s0[0][2], s0[0][3]);
        float mxC = fmaxf(s1[0][0], s1[0][1]), mxD = fmaxf(s1[0][2], s1[0][3]);
#pragma unroll
        for (int nt = 1; nt < 8; nt++) {
            mxA = fmaxf(mxA, fmaxf(s0[nt][0], s0[nt][1]));
            mxB = fmaxf(mxB, fmaxf(s0[nt][2], s0[nt][3]));
            mxC = fmaxf(mxC, fmaxf(s1[nt][0], s1[nt][1]));
            mxD = fmaxf(mxD, fmaxf(s1[nt][2], s1[nt][3]));
        }
        mxA = fmaxf(mxA, __shfl_xor_sync(~0u, mxA, 1));
        mxA = fmaxf(mxA, __shfl_xor_sync(~0u, mxA, 2));
        mxB = fmaxf(mxB, __shfl_xor_sync(~0u, mxB, 1));
        mxB = fmaxf(mxB, __shfl_xor_sync(~0u, mxB, 2));
        mxC = fmaxf(mxC, __shfl_xor_sync(~0u, mxC, 1));
        mxC = fmaxf(mxC, __shfl_xor_sync(~0u, mxC, 2));
        mxD = fmaxf(mxD, __shfl_xor_sync(~0u, mxD, 1));
        mxD = fmaxf(mxD, __shfl_xor_sync(~0u, mxD, 2));
        float mnA = fmaxf(mrA, mxA), mnB = fmaxf(mrB, mxB);
        float mnC = fmaxf(mrC, mxC), mnD = fmaxf(mrD, mxD);
        float cA = exp2f(mrA - mnA), cB = exp2f(mrB - mnB);
        float cC = exp2f(mrC - mnC), cD = exp2f(mrD - mnD);
        float sA = 0.f, sB = 0.f, sC = 0.f, sD = 0.f;
#pragma unroll
        for (int nt = 0; nt < 8; nt++) {
            float p00 = exp2f(s0[nt][0] - mnA), p01 = exp2f(s0[nt][1] - mnA);
            float p02 = exp2f(s0[nt][2] - mnB), p03 = exp2f(s0[nt][3] - mnB);
            float p10 = exp2f(s1[nt][0] - mnC), p11 = exp2f(s1[nt][1] - mnC);
            float p12 = exp2f(s1[nt][2] - mnD), p13 = exp2f(s1[nt][3] - mnD);
            sA += p00 + p01; sB += p02 + p03; sC += p10 + p11; sD += p12 + p13;
            *(uint2*)&Ps[(wm + g) * PTS + nt * 8 + 2 * qd] =
                make_uint2(pgqa_tf32r(p00), pgqa_tf32r(p01));
            *(uint2*)&Ps[(wm + g + 8) * PTS + nt * 8 + 2 * qd] =
                make_uint2(pgqa_tf32r(p02), pgqa_tf32r(p03));
            *(uint2*)&Ps[(64 + wm + g) * PTS + nt * 8 + 2 * qd] =
                make_uint2(pgqa_tf32r(p10), pgqa_tf32r(p11));
            *(uint2*)&Ps[(64 + wm + g + 8) * PTS + nt * 8 + 2 * qd] =
                make_uint2(pgqa_tf32r(p12), pgqa_tf32r(p13));
            o0[nt][0] *= cA; o0[nt][1] *= cA; o0[nt][2] *= cB; o0[nt][3] *= cB;
            o1[nt][0] *= cC; o1[nt][1] *= cC; o1[nt][2] *= cD; o1[nt][3] *= cD;
        }
        sA += __shfl_xor_sync(~0u, sA, 1); sA += __shfl_xor_sync(~0u, sA, 2);
        sB += __shfl_xor_sync(~0u, sB, 1); sB += __shfl_xor_sync(~0u, sB, 2);
        sC += __shfl_xor_sync(~0u, sC, 1); sC += __shfl_xor_sync(~0u, sC, 2);
        sD += __shfl_xor_sync(~0u, sD, 1); sD += __shfl_xor_sync(~0u, sD, 2);
        lrA = lrA * cA + sA; lrB = lrB * cB + sB;
        lrC = lrC * cC + sC; lrD = lrD * cD + sD;
        mrA = mnA; mrB = mnB; mrC = mnC; mrD = mnD;
        __syncwarp();

#pragma unroll
        for (int k8 = 0; k8 < 8; k8++) {
            unsigned pa00 = Ps[(wm + g) * PTS + k8 * 8 + qd];
            unsigned pa01 = Ps[(wm + g + 8) * PTS + k8 * 8 + qd];
            unsigned pa02 = Ps[(wm + g) * PTS + k8 * 8 + qd + 4];
            unsigned pa03 = Ps[(wm + g + 8) * PTS + k8 * 8 + qd + 4];
            unsigned pa10 = Ps[(64 + wm + g) * PTS + k8 * 8 + qd];
            unsigned pa11 = Ps[(64 + wm + g + 8) * PTS + k8 * 8 + qd];
            unsigned pa12 = Ps[(64 + wm + g) * PTS + k8 * 8 + qd + 4];
            unsigned pa13 = Ps[(64 + wm + g + 8) * PTS + k8 * 8 + qd + 4];
            const unsigned* Vk0 = &Vb[(k8 * 8 + qd) * VTS];
            const unsigned* Vk1 = &Vb[(k8 * 8 + qd + 4) * VTS];
#pragma unroll
            for (int nt = 0; nt < 8; nt++) {
                unsigned b0 = Vk0[nt * 8 + g];
                unsigned b1 = Vk1[nt * 8 + g];
                pgqa_mma_tf32(o0[nt][0], o0[nt][1], o0[nt][2], o0[nt][3],
                              pa00, pa01, pa02, pa03, b0, b1);
                pgqa_mma_tf32(o1[nt][0], o1[nt][1], o1[nt][2], o1[nt][3],
                              pa10, pa11, pa12, pa13, b0, b1);
            }
        }
        __syncthreads();
        if (tk + 1 < NT) {
            issue_v(tk + 1);
            asm volatile("cp.async.commit_group;" ::: "memory");
        }
    }

    float iA = 1.f / lrA, iB = 1.f / lrB, iC = 1.f / lrC, iD = 1.f / lrD;
    const int h0 = kvh * 2, h1 = kvh * 2 + 1;
    float* OA = Out + ((size_t)(b * NP + q0 + wm + g)) * PD;
    float* OB = Out + ((size_t)(b * NP + q0 + wm + g + 8)) * PD;
    double sh0 = 0.0, sq0 = 0.0, sh1 = 0.0, sq1 = 0.0;
#pragma unroll
    for (int nt = 0; nt < 8; nt++) {
        int c = nt * 8 + qd * 2;
        float a0 = o0[nt][0] * iA, a1 = o0[nt][1] * iA;
        float b0v = o0[nt][2] * iB, b1v = o0[nt][3] * iB;
        float c0v = o1[nt][0] * iC, c1v = o1[nt][1] * iC;
        float d0v = o1[nt][2] * iD, d1v = o1[nt][3] * iD;
        *(float2*)(OA + h0 * HD + c) = make_float2(a0, a1);
        *(float2*)(OB + h0 * HD + c) = make_float2(b0v, b1v);
        *(float2*)(OA + h1 * HD + c) = make_float2(c0v, c1v);
        *(float2*)(OB + h1 * HD + c) = make_float2(d0v, d1v);
        sh0 += (double)a0 + a1 + b0v + b1v;
        sq0 += (double)a0 * a0 + (double)a1 * a1 + (double)b0v * b0v + (double)b1v * b1v;
        sh1 += (double)c0v + c1v + d0v + d1v;
        sq1 += (double)c0v * c0v + (double)c1v * c1v + (double)d0v * d0v + (double)d1v * d1v;
    }
    double* dsc = (double*)atsm;
    __syncthreads();
    dsc[t] = sh0; dsc[128 + t] = sq0; dsc[256 + t] = sh1; dsc[384 + t] = sq1;
    __syncthreads();
    for (int st = 64; st > 0; st >>= 1) {
        if (t < st) {
            dsc[t] += dsc[t + st];
            dsc[128 + t] += dsc[128 + t + st];
            dsc[256 + t] += dsc[256 + t + st];
            dsc[384 + t] += dsc[384 + t + st];
        }
        __syncthreads();
    }
    if (t == 0) {
        int bh0 = b * NH + h0, bh1 = b * NH + h1, qt = blockIdx.x;
        pgqa_rsum[bh0 * 16 + qt] = dsc[0];
        pgqa_rsum2[bh0 * 16 + qt] = dsc[128];
        pgqa_rsum[bh1 * 16 + qt] = dsc[256];
        pgqa_rsum2[bh1 * 16 + qt] = dsc[384];
    }
}

// -------- finalize both stat sets --------------------------------------------
__global__ void pgqa_sfin() {
    int tid = threadIdx.x;   // 96
    if (tid < NH) {
        double sm = 0.0, sm2 = 0.0;
#pragma unroll
        for (int s = 0; s < 8; s++) { sm += pgqa_msum[tid * 8 + s]; sm2 += pgqa_msum2[tid * 8 + s]; }
        double n = (double)YLEN;
        double mean = sm / n;
        double var = (sm2 - sm * sm / n) / (n - 1.0);
        double sd = sqrt(var > 0.0 ? var : 0.0);
        if (sd == 0.0) sd = 1.0;
        pgqa_mmean[tid] = (float)mean;
        pgqa_mistd[tid] = (float)(1.0 / sd);
    }
    if (tid < NB * NH) {
        double sm = 0.0, sm2 = 0.0;
#pragma unroll
        for (int s = 0; s < 16; s++) { sm += pgqa_rsum[tid * 16 + s]; sm2 += pgqa_rsum2[tid * 16 + s]; }
        double n = (double)YLEN;
        double mean = sm / n;
        double var = (sm2 - sm * sm / n) / (n - 1.0);
        pgqa_rmean[tid] = (float)mean;
        pgqa_rstd[tid] = (float)sqrt(var > 0.0 ? var : 0.0);
    }
}

// ---------------- launcher ---------------------------------------------------
extern "C" void kernel_launch(void* const* d_in, const int* in_sizes, int n_in,
                              void* d_out, int out_size) {
    const float* x  = (const float*)d_in[0];
    const float* Wq = (const float*)d_in[1];
    const float* Wk = (const float*)d_in[2];
    const float* Wv = (const float*)d_in[3];
    const float* Wp = (const float*)d_in[4];
    const float* bp = (const float*)d_in[5];
    float* out = (float*)d_out;

    float *Qb, *Kb, *Vb, *Ab;
    cudaGetSymbolAddress((void**)&Qb, pgqa_Q);
    cudaGetSymbolAddress((void**)&Kb, pgqa_K);
    cudaGetSymbolAddress((void**)&Vb, pgqa_V);
    cudaGetSymbolAddress((void**)&Ab, pgqa_Att);

    cudaFuncSetAttribute(pgqa_attn_mma, cudaFuncAttributeMaxDynamicSharedMemorySize, ATTN_SMEM_BYTES);
    cudaFuncSetAttribute(pgqa_qkv_mgen, cudaFuncAttributeMaxDynamicSharedMemorySize, GSMEM_BYTES);
    cudaFuncSetAttribute(pgqa_proj_mma, cudaFuncAttributeMaxDynamicSharedMemorySize, GSMEM_BYTES);

    // tf32 pre-round of x and all weights
    pgqa_prep<<<1184, 256>>>(x, Wq, Wk, Wv, Wp);

    // M gen/stats (blocks 0-95) + fused q/k/v projections (blocks 96-863)
    pgqa_qkv_mgen<<<96 + 12 * (BPROWS / 128), 256, GSMEM_BYTES>>>(Qb, Kb, Vb);

    // flash attention (with fused per-(b,h) output stat partials)
    pgqa_attn_mma<<<dim3(NP / 64, NB * NKV), 128, ATTN_SMEM_BYTES>>>(Qb, Kb, Vb, Ab);

    // finalize M stats + row stats
    pgqa_sfin<<<1, 96>>>();

    // noise subtraction (tf32-pre-rounded X2)
    pgqa_noise<<<(BPROWS * PD / 4) / 256, 256>>>(Ab);

    // output projection (+bias), raw tf32 operands
    pgqa_proj_mma<<<dim3(PD / 128, BPROWS / 128), 256, GSMEM_BYTES>>>(bp, out);
}